// round 1
// baseline (speedup 1.0000x reference)
#include <cuda_runtime.h>
#include <math.h>

#define EMBED   1024
#define NHEADS  16
#define HDIM    64
#define SEQ     2048
#define BATCH   2
#define MTOT    (BATCH * SEQ)      // 4096
#define QKVDIM  (3 * EMBED)        // 3072
#define ATTN_SCALE 0.125f          // 64^-0.5

// Scratch (allocation-free: __device__ globals)
__device__ float g_qkv [ (size_t)MTOT * QKVDIM ];   // [4096, 3072]
__device__ float g_attn[ (size_t)MTOT * EMBED  ];   // [4096, 1024]

// ---------------------------------------------------------------------------
// SGEMM:  C[m,n] = sum_k A[m*K+k] * B[n*K+k]  (+ bias[n])
// A: [M,K] row-major, B: [N,K] row-major (i.e. C = A @ B^T). All dims % 128/16.
// Block 128x128, BK=16, 256 threads, 8x8 per-thread tile.
// ---------------------------------------------------------------------------
__global__ __launch_bounds__(256, 2)
void sgemm_nt(const float* __restrict__ A, const float* __restrict__ B,
              const float* __restrict__ bias, float* __restrict__ C,
              int M, int N, int K)
{
    const int BM = 128, BN = 128, BK = 16;
    __shared__ float As[BK][BM];
    __shared__ float Bs[BK][BN];

    const int bm = blockIdx.y * BM;
    const int bn = blockIdx.x * BN;
    const int tid = threadIdx.x;
    const int tm = (tid / 16) * 8;
    const int tn = (tid % 16) * 8;

    float acc[8][8];
#pragma unroll
    for (int i = 0; i < 8; i++)
#pragma unroll
        for (int j = 0; j < 8; j++) acc[i][j] = 0.f;

    for (int k0 = 0; k0 < K; k0 += BK) {
        // load 128x16 tiles of A and B (as float4), store transposed [k][m]
#pragma unroll
        for (int it = 0; it < 2; it++) {
            int idx = tid + it * 256;        // 0..511 float4 slots
            int row = idx >> 2;              // 0..127
            int c4  = idx & 3;               // 0..3
            float4 va = *reinterpret_cast<const float4*>(
                &A[(size_t)(bm + row) * K + k0 + c4 * 4]);
            As[c4*4+0][row] = va.x; As[c4*4+1][row] = va.y;
            As[c4*4+2][row] = va.z; As[c4*4+3][row] = va.w;
            float4 vb = *reinterpret_cast<const float4*>(
                &B[(size_t)(bn + row) * K + k0 + c4 * 4]);
            Bs[c4*4+0][row] = vb.x; Bs[c4*4+1][row] = vb.y;
            Bs[c4*4+2][row] = vb.z; Bs[c4*4+3][row] = vb.w;
        }
        __syncthreads();

#pragma unroll
        for (int k = 0; k < BK; k++) {
            float a[8], b[8];
#pragma unroll
            for (int i = 0; i < 8; i++) a[i] = As[k][tm + i];
#pragma unroll
            for (int j = 0; j < 8; j++) b[j] = Bs[k][tn + j];
#pragma unroll
            for (int i = 0; i < 8; i++)
#pragma unroll
                for (int j = 0; j < 8; j++)
                    acc[i][j] = fmaf(a[i], b[j], acc[i][j]);
        }
        __syncthreads();
    }

    float bsum[8];
#pragma unroll
    for (int j = 0; j < 8; j++) bsum[j] = bias ? bias[bn + tn + j] : 0.f;

#pragma unroll
    for (int i = 0; i < 8; i++) {
        float4 v0 = make_float4(acc[i][0]+bsum[0], acc[i][1]+bsum[1],
                                acc[i][2]+bsum[2], acc[i][3]+bsum[3]);
        float4 v1 = make_float4(acc[i][4]+bsum[4], acc[i][5]+bsum[5],
                                acc[i][6]+bsum[6], acc[i][7]+bsum[7]);
        float* cp = &C[(size_t)(bm + tm + i) * N + bn + tn];
        *reinterpret_cast<float4*>(cp)     = v0;
        *reinterpret_cast<float4*>(cp + 4) = v1;
    }
}

// ---------------------------------------------------------------------------
// Flash attention (fp32, online softmax).
// qkv layout: [b, n, 3*EMBED] with q at +0, k at +1024, v at +2048, head h at +h*64.
// Grid: (SEQ/128, NHEADS, BATCH). 128 threads; thread t owns query row q0+t.
// smem: K tile [64][64], V tile [64][64], S buffer [64][128] (key-major, conflict-free).
// ---------------------------------------------------------------------------
#define ATTN_SMEM_FLOATS (64*64 + 64*64 + 64*128)   // 16384 floats = 64 KB

__global__ __launch_bounds__(128, 3)
void attn_kernel(const float* __restrict__ qkv, float* __restrict__ out)
{
    extern __shared__ float sm[];
    float* Ks = sm;                 // [64][64]
    float* Vs = sm + 64 * 64;       // [64][64]
    float* Ss = sm + 2 * 64 * 64;   // [64][128]  Ss[j*128 + tid]

    const int b   = blockIdx.z;
    const int h   = blockIdx.y;
    const int q0  = blockIdx.x * 128;
    const int tid = threadIdx.x;
    const int n   = q0 + tid;

    const float* qptr = qkv + ((size_t)(b * SEQ + n)) * QKVDIM + h * HDIM;
    float4 q[16];
#pragma unroll
    for (int i = 0; i < 16; i++)
        q[i] = *reinterpret_cast<const float4*>(qptr + i * 4);

    float4 o[16];
#pragma unroll
    for (int i = 0; i < 16; i++) o[i] = make_float4(0.f, 0.f, 0.f, 0.f);
    float mrun = -INFINITY, lrun = 0.f;

    for (int kk0 = 0; kk0 < SEQ; kk0 += 64) {
        const float* kbase = qkv + ((size_t)(b * SEQ + kk0)) * QKVDIM + EMBED     + h * HDIM;
        const float* vbase = qkv + ((size_t)(b * SEQ + kk0)) * QKVDIM + 2 * EMBED + h * HDIM;
        // cooperative tile load: 64 rows x 16 float4 = 1024 float4, 128 threads x 8
#pragma unroll
        for (int it = 0; it < 8; it++) {
            int idx = tid + it * 128;      // 0..1023
            int row = idx >> 4;
            int c4  = idx & 15;
            *reinterpret_cast<float4*>(&Ks[row * 64 + c4 * 4]) =
                *reinterpret_cast<const float4*>(kbase + (size_t)row * QKVDIM + c4 * 4);
            *reinterpret_cast<float4*>(&Vs[row * 64 + c4 * 4]) =
                *reinterpret_cast<const float4*>(vbase + (size_t)row * QKVDIM + c4 * 4);
        }
        __syncthreads();

        // pass 1: scores for 64 keys (K rows broadcast across the warp)
        float tmax = -INFINITY;
#pragma unroll 2
        for (int j = 0; j < 64; j++) {
            const float4* krow = reinterpret_cast<const float4*>(&Ks[j * 64]);
            float s = 0.f;
#pragma unroll
            for (int i = 0; i < 16; i++) {
                float4 kv = krow[i];
                s = fmaf(q[i].x, kv.x, s);
                s = fmaf(q[i].y, kv.y, s);
                s = fmaf(q[i].z, kv.z, s);
                s = fmaf(q[i].w, kv.w, s);
            }
            s *= ATTN_SCALE;
            Ss[j * 128 + tid] = s;
            tmax = fmaxf(tmax, s);
        }

        const float mnew = fmaxf(mrun, tmax);
        const float corr = __expf(mrun - mnew);
        mrun = mnew;
        lrun *= corr;
#pragma unroll
        for (int i = 0; i < 16; i++) {
            o[i].x *= corr; o[i].y *= corr; o[i].z *= corr; o[i].w *= corr;
        }

        // pass 2: accumulate P @ V
#pragma unroll 2
        for (int j = 0; j < 64; j++) {
            float p = __expf(Ss[j * 128 + tid] - mnew);
            lrun += p;
            const float4* vrow = reinterpret_cast<const float4*>(&Vs[j * 64]);
#pragma unroll
            for (int i = 0; i < 16; i++) {
                float4 vv = vrow[i];
                o[i].x = fmaf(p, vv.x, o[i].x);
                o[i].y = fmaf(p, vv.y, o[i].y);
                o[i].z = fmaf(p, vv.z, o[i].z);
                o[i].w = fmaf(p, vv.w, o[i].w);
            }
        }
        __syncthreads();
    }

    const float inv = 1.f / lrun;
    float* optr = out + ((size_t)(b * SEQ + n)) * EMBED + h * HDIM;
#pragma unroll
    for (int i = 0; i < 16; i++) {
        float4 v = o[i];
        v.x *= inv; v.y *= inv; v.z *= inv; v.w *= inv;
        *reinterpret_cast<float4*>(optr + i * 4) = v;
    }
}

// ---------------------------------------------------------------------------
extern "C" void kernel_launch(void* const* d_in, const int* in_sizes, int n_in,
                              void* d_out, int out_size)
{
    const float* x     = (const float*)d_in[0];   // [2,2048,1024]
    const float* w_qkv = (const float*)d_in[1];   // [3072,1024]
    const float* w_out = (const float*)d_in[2];   // [1024,1024]
    const float* b_out = (const float*)d_in[3];   // [1024]
    float* out = (float*)d_out;                   // [2,2048,1024]

    float *qkv_ptr = nullptr, *attn_ptr = nullptr;
    cudaGetSymbolAddress((void**)&qkv_ptr,  g_qkv);
    cudaGetSymbolAddress((void**)&attn_ptr, g_attn);

    // 1) QKV projection: [4096,3072] = x[4096,1024] @ w_qkv^T
    {
        dim3 grid(QKVDIM / 128, MTOT / 128);
        sgemm_nt<<<grid, 256>>>(x, w_qkv, nullptr, qkv_ptr, MTOT, QKVDIM, EMBED);
    }

    // 2) Flash attention
    {
        const size_t smem = ATTN_SMEM_FLOATS * sizeof(float);  // 65536
        cudaFuncSetAttribute(attn_kernel,
                             cudaFuncAttributeMaxDynamicSharedMemorySize, (int)smem);
        dim3 grid(SEQ / 128, NHEADS, BATCH);
        attn_kernel<<<grid, 128, smem>>>(qkv_ptr, attn_ptr);
    }

    // 3) Output projection + bias: [4096,1024] = attn[4096,1024] @ w_out^T + b
    {
        dim3 grid(EMBED / 128, MTOT / 128);
        sgemm_nt<<<grid, 256>>>(attn_ptr, w_out, b_out, out, MTOT, EMBED, EMBED);
    }
}

// round 3
// speedup vs baseline: 1.3135x; 1.3135x over previous
#include <cuda_runtime.h>
#include <cuda_bf16.h>
#include <math.h>
#include <stdint.h>

#define EMBED   1024
#define NHEADS  16
#define HDIM    64
#define SEQ     2048
#define BATCH   2
#define MTOT    (BATCH * SEQ)      // 4096
#define QKVDIM  (3 * EMBED)        // 3072
#define GK      1024
#define ATTN_SCALE 0.125f

typedef unsigned long long u64;

// ---------------------------------------------------------------------------
// Scratch (allocation-free: __device__ globals)
// ---------------------------------------------------------------------------
__device__ float g_qkv [(size_t)MTOT * QKVDIM];
__device__ float g_attn[(size_t)MTOT * EMBED ];
__device__ __nv_bfloat16 g_xh [(size_t)MTOT  * EMBED];
__device__ __nv_bfloat16 g_xl [(size_t)MTOT  * EMBED];
__device__ __nv_bfloat16 g_wqh[(size_t)QKVDIM* EMBED];
__device__ __nv_bfloat16 g_wql[(size_t)QKVDIM* EMBED];
__device__ __nv_bfloat16 g_woh[(size_t)EMBED * EMBED];
__device__ __nv_bfloat16 g_wol[(size_t)EMBED * EMBED];
__device__ __nv_bfloat16 g_ah [(size_t)MTOT  * EMBED];
__device__ __nv_bfloat16 g_al [(size_t)MTOT  * EMBED];

// ---------------------------------------------------------------------------
// helpers
// ---------------------------------------------------------------------------
__device__ __forceinline__ uint32_t smem_u32(const void* p) {
    uint32_t a;
    asm("{ .reg .u64 t; cvta.to.shared.u64 t, %1; cvt.u32.u64 %0, t; }" : "=r"(a) : "l"(p));
    return a;
}
__device__ __forceinline__ void cp16(uint32_t s, const void* g) {
    asm volatile("cp.async.cg.shared.global [%0], [%1], 16;" :: "r"(s), "l"(g));
}
__device__ __forceinline__ void mma16816(float* c, const uint32_t* a, const uint32_t* b) {
    asm volatile(
        "mma.sync.aligned.m16n8k16.row.col.f32.bf16.bf16.f32 "
        "{%0,%1,%2,%3}, {%4,%5,%6,%7}, {%8,%9}, {%0,%1,%2,%3};"
        : "+f"(c[0]), "+f"(c[1]), "+f"(c[2]), "+f"(c[3])
        : "r"(a[0]), "r"(a[1]), "r"(a[2]), "r"(a[3]), "r"(b[0]), "r"(b[1]));
}
// packed fp32x2
__device__ __forceinline__ u64 ffma2(u64 a, u64 b, u64 c) {
    u64 d; asm("fma.rn.f32x2 %0, %1, %2, %3;" : "=l"(d) : "l"(a), "l"(b), "l"(c)); return d;
}
__device__ __forceinline__ u64 fmul2(u64 a, u64 b) {
    u64 d; asm("mul.rn.f32x2 %0, %1, %2;" : "=l"(d) : "l"(a), "l"(b)); return d;
}
__device__ __forceinline__ u64 pack2(float x, float y) {
    u64 d; asm("mov.b64 %0, {%1, %2};" : "=l"(d) : "f"(x), "f"(y)); return d;
}
__device__ __forceinline__ void unpack2(u64 v, float& x, float& y) {
    asm("mov.b64 {%0, %1}, %2;" : "=f"(x), "=f"(y) : "l"(v));
}

// ---------------------------------------------------------------------------
// fp32 -> (bf16 hi, bf16 lo) split
// ---------------------------------------------------------------------------
__global__ void cvt_split(const float* __restrict__ in, __nv_bfloat16* __restrict__ hi,
                          __nv_bfloat16* __restrict__ lo, int n4)
{
    int i = blockIdx.x * blockDim.x + threadIdx.x;
    if (i >= n4) return;
    float4 v = reinterpret_cast<const float4*>(in)[i];
    __nv_bfloat16 h0 = __float2bfloat16(v.x), h1 = __float2bfloat16(v.y);
    __nv_bfloat16 h2 = __float2bfloat16(v.z), h3 = __float2bfloat16(v.w);
    __nv_bfloat16 l0 = __float2bfloat16(v.x - __bfloat162float(h0));
    __nv_bfloat16 l1 = __float2bfloat16(v.y - __bfloat162float(h1));
    __nv_bfloat16 l2 = __float2bfloat16(v.z - __bfloat162float(h2));
    __nv_bfloat16 l3 = __float2bfloat16(v.w - __bfloat162float(h3));
    __nv_bfloat162 hA = {h0, h1}, hB = {h2, h3}, lA = {l0, l1}, lB = {l2, l3};
    uint2 hv, lv;
    hv.x = *reinterpret_cast<uint32_t*>(&hA); hv.y = *reinterpret_cast<uint32_t*>(&hB);
    lv.x = *reinterpret_cast<uint32_t*>(&lA); lv.y = *reinterpret_cast<uint32_t*>(&lB);
    reinterpret_cast<uint2*>(hi)[i] = hv;
    reinterpret_cast<uint2*>(lo)[i] = lv;
}

// ---------------------------------------------------------------------------
// HMMA bf16x3 GEMM: C[m,n] = sum_k A[m,k]*B[n,k] (+bias[n])
// A,B as (hi,lo) bf16 pairs, K-major. CTA 128x128, BK=32, 256 threads.
// Warp grid 4(m) x 2(n): warp tile 32x64. mma.sync.m16n8k16.
// ---------------------------------------------------------------------------
#define BK    32
#define LDT   48                 // BK + 16 pad (keeps 16B-aligned rows)
#define TS_H  (128 * LDT)        // halves per tile
#define STG_H (4 * TS_H)         // halves per stage (Ah,Al,Bh,Bl)

__global__ __launch_bounds__(256, 1)
void gemm_bf16x3(const __nv_bfloat16* __restrict__ Ah, const __nv_bfloat16* __restrict__ Al,
                 const __nv_bfloat16* __restrict__ Bh, const __nv_bfloat16* __restrict__ Bl,
                 const float* __restrict__ bias, float* __restrict__ C,
                 int M, int N, int K)
{
    extern __shared__ __align__(16) __nv_bfloat16 sm[];   // 2 stages x 4 tiles x [128][48]

    const int tid  = threadIdx.x;
    const int wid  = tid >> 5, lane = tid & 31;
    const int bm   = blockIdx.y * 128, bn = blockIdx.x * 128;
    const int wm   = (wid & 3) * 32;        // warp m offset in CTA tile
    const int wn   = (wid >> 2) * 64;       // warp n offset
    const int g    = lane >> 2;             // group id 0..7
    const int cp2  = (lane & 3) * 2;        // k col pair base

    const uint32_t sb = smem_u32(sm);

    const __nv_bfloat16* gsrc[4] = {
        Ah + (size_t)bm * K, Al + (size_t)bm * K,
        Bh + (size_t)bn * K, Bl + (size_t)bn * K };

    float acc[2][8][4];
#pragma unroll
    for (int i = 0; i < 2; i++)
#pragma unroll
        for (int j = 0; j < 8; j++)
#pragma unroll
            for (int l = 0; l < 4; l++) acc[i][j][l] = 0.f;

    const int nch = K >> 5;   // K / 32

    auto stage_load = [&](int c, int s) {
#pragma unroll
        for (int t = 0; t < 4; t++) {
            const __nv_bfloat16* bp = gsrc[t] + c * BK;
#pragma unroll
            for (int it = 0; it < 2; it++) {
                int idx = it * 256 + tid;          // 0..511
                int row = idx >> 2, cc = idx & 3;  // 4 x 16B per row
                uint32_t so = sb + (uint32_t)(s * STG_H + t * TS_H + row * LDT + cc * 8) * 2;
                cp16(so, bp + (size_t)row * K + cc * 8);
            }
        }
        asm volatile("cp.async.commit_group;");
    };

    stage_load(0, 0);

    for (int c = 0; c < nch; c++) {
        const int s = c & 1;
        if (c + 1 < nch) {
            stage_load(c + 1, s ^ 1);
            asm volatile("cp.async.wait_group 1;");
        } else {
            asm volatile("cp.async.wait_group 0;");
        }
        __syncthreads();

        const int aoff = s * STG_H;               // Ah tile
        const int boff = s * STG_H + 2 * TS_H;    // Bh tile

#pragma unroll
        for (int kk = 0; kk < BK; kk += 16) {
            uint32_t af[2][2][4];   // [mtile][hi/lo][4]
            uint32_t bf[8][2][2];   // [ntile][hi/lo][2]
#pragma unroll
            for (int mt = 0; mt < 2; mt++) {
                int r0 = wm + mt * 16 + g;
#pragma unroll
                for (int hl = 0; hl < 2; hl++) {
                    const __nv_bfloat16* base = &sm[aoff + hl * TS_H];
                    af[mt][hl][0] = *(const uint32_t*)&base[(r0    ) * LDT + kk + cp2    ];
                    af[mt][hl][1] = *(const uint32_t*)&base[(r0 + 8) * LDT + kk + cp2    ];
                    af[mt][hl][2] = *(const uint32_t*)&base[(r0    ) * LDT + kk + cp2 + 8];
                    af[mt][hl][3] = *(const uint32_t*)&base[(r0 + 8) * LDT + kk + cp2 + 8];
                }
            }
#pragma unroll
            for (int nt = 0; nt < 8; nt++) {
                int rb = wn + nt * 8 + g;
#pragma unroll
                for (int hl = 0; hl < 2; hl++) {
                    const __nv_bfloat16* base = &sm[boff + hl * TS_H];
                    bf[nt][hl][0] = *(const uint32_t*)&base[rb * LDT + kk + cp2    ];
                    bf[nt][hl][1] = *(const uint32_t*)&base[rb * LDT + kk + cp2 + 8];
                }
            }
#pragma unroll
            for (int mt = 0; mt < 2; mt++)
#pragma unroll
                for (int nt = 0; nt < 8; nt++) {
                    mma16816(acc[mt][nt], af[mt][0], bf[nt][0]);  // Ah*Bh
                    mma16816(acc[mt][nt], af[mt][0], bf[nt][1]);  // Ah*Bl
                    mma16816(acc[mt][nt], af[mt][1], bf[nt][0]);  // Al*Bh
                }
        }
        __syncthreads();
    }

    // epilogue
#pragma unroll
    for (int nt = 0; nt < 8; nt++) {
        int col = bn + wn + nt * 8 + cp2;
        float b0 = 0.f, b1 = 0.f;
        if (bias) { b0 = bias[col]; b1 = bias[col + 1]; }
#pragma unroll
        for (int mt = 0; mt < 2; mt++) {
            int r0 = bm + wm + mt * 16 + g;
            float2 v0 = make_float2(acc[mt][nt][0] + b0, acc[mt][nt][1] + b1);
            float2 v1 = make_float2(acc[mt][nt][2] + b0, acc[mt][nt][3] + b1);
            *reinterpret_cast<float2*>(&C[(size_t)r0 * N + col])       = v0;
            *reinterpret_cast<float2*>(&C[(size_t)(r0 + 8) * N + col]) = v1;
        }
    }
}

// ---------------------------------------------------------------------------
// Flash attention, fp32 with packed fma.rn.f32x2.
// ---------------------------------------------------------------------------
#define ATTN_SMEM_FLOATS (64*64 + 64*64 + 64*128)   // 64 KB

__global__ __launch_bounds__(128, 3)
void attn_kernel(const float* __restrict__ qkv, float* __restrict__ out)
{
    extern __shared__ float smf[];
    float* Ks = smf;
    float* Vs = smf + 64 * 64;
    float* Ss = smf + 2 * 64 * 64;

    const int b   = blockIdx.z;
    const int h   = blockIdx.y;
    const int q0  = blockIdx.x * 128;
    const int tid = threadIdx.x;
    const int n   = q0 + tid;

    const u64 scale2 = pack2(ATTN_SCALE, ATTN_SCALE);

    const float* qptr = qkv + ((size_t)(b * SEQ + n)) * QKVDIM + h * HDIM;
    u64 q2[32];
    {
        const ulonglong2* qp = reinterpret_cast<const ulonglong2*>(qptr);
#pragma unroll
        for (int i = 0; i < 16; i++) {
            ulonglong2 t = qp[i];
            q2[2 * i]     = fmul2(t.x, scale2);
            q2[2 * i + 1] = fmul2(t.y, scale2);
        }
    }

    u64 o2[32];
#pragma unroll
    for (int i = 0; i < 32; i++) o2[i] = 0ULL;
    float mrun = -INFINITY, lrun = 0.f;

    for (int kk0 = 0; kk0 < SEQ; kk0 += 64) {
        const float* kbase = qkv + ((size_t)(b * SEQ + kk0)) * QKVDIM + EMBED     + h * HDIM;
        const float* vbase = qkv + ((size_t)(b * SEQ + kk0)) * QKVDIM + 2 * EMBED + h * HDIM;
#pragma unroll
        for (int it = 0; it < 8; it++) {
            int idx = tid + it * 128;
            int row = idx >> 4;
            int c4  = idx & 15;
            *reinterpret_cast<float4*>(&Ks[row * 64 + c4 * 4]) =
                *reinterpret_cast<const float4*>(kbase + (size_t)row * QKVDIM + c4 * 4);
            *reinterpret_cast<float4*>(&Vs[row * 64 + c4 * 4]) =
                *reinterpret_cast<const float4*>(vbase + (size_t)row * QKVDIM + c4 * 4);
        }
        __syncthreads();

        float tmax = -INFINITY;
#pragma unroll 2
        for (int j = 0; j < 64; j++) {
            const ulonglong2* kr = reinterpret_cast<const ulonglong2*>(&Ks[j * 64]);
            u64 acc0 = 0ULL, acc1 = 0ULL;
#pragma unroll
            for (int i = 0; i < 16; i++) {
                ulonglong2 kv = kr[i];
                acc0 = ffma2(q2[2 * i],     kv.x, acc0);
                acc1 = ffma2(q2[2 * i + 1], kv.y, acc1);
            }
            float a0, a1, b0, b1;
            unpack2(acc0, a0, a1);
            unpack2(acc1, b0, b1);
            float s = (a0 + a1) + (b0 + b1);
            Ss[j * 128 + tid] = s;
            tmax = fmaxf(tmax, s);
        }

        const float mnew = fmaxf(mrun, tmax);
        const float corr = __expf(mrun - mnew);
        mrun = mnew;
        lrun *= corr;
        {
            const u64 corr2 = pack2(corr, corr);
#pragma unroll
            for (int i = 0; i < 32; i++) o2[i] = fmul2(o2[i], corr2);
        }

#pragma unroll 2
        for (int j = 0; j < 64; j++) {
            float p = __expf(Ss[j * 128 + tid] - mnew);
            lrun += p;
            const u64 p2 = pack2(p, p);
            const ulonglong2* vr = reinterpret_cast<const ulonglong2*>(&Vs[j * 64]);
#pragma unroll
            for (int i = 0; i < 16; i++) {
                ulonglong2 vv = vr[i];
                o2[2 * i]     = ffma2(p2, vv.x, o2[2 * i]);
                o2[2 * i + 1] = ffma2(p2, vv.y, o2[2 * i + 1]);
            }
        }
        __syncthreads();
    }

    const float inv = 1.f / lrun;
    const u64 inv2 = pack2(inv, inv);
    float* optr = out + ((size_t)(b * SEQ + n)) * EMBED + h * HDIM;
    ulonglong2* op = reinterpret_cast<ulonglong2*>(optr);
#pragma unroll
    for (int i = 0; i < 16; i++) {
        ulonglong2 t;
        t.x = fmul2(o2[2 * i], inv2);
        t.y = fmul2(o2[2 * i + 1], inv2);
        op[i] = t;
    }
}

// ---------------------------------------------------------------------------
extern "C" void kernel_launch(void* const* d_in, const int* in_sizes, int n_in,
                              void* d_out, int out_size)
{
    const float* x     = (const float*)d_in[0];
    const float* w_qkv = (const float*)d_in[1];
    const float* w_out = (const float*)d_in[2];
    const float* b_out = (const float*)d_in[3];
    float* out = (float*)d_out;

    float *qkv_ptr, *attn_ptr;
    __nv_bfloat16 *xh, *xl, *wqh, *wql, *woh, *wol, *ah, *al;
    cudaGetSymbolAddress((void**)&qkv_ptr,  g_qkv);
    cudaGetSymbolAddress((void**)&attn_ptr, g_attn);
    cudaGetSymbolAddress((void**)&xh,  g_xh);  cudaGetSymbolAddress((void**)&xl,  g_xl);
    cudaGetSymbolAddress((void**)&wqh, g_wqh); cudaGetSymbolAddress((void**)&wql, g_wql);
    cudaGetSymbolAddress((void**)&woh, g_woh); cudaGetSymbolAddress((void**)&wol, g_wol);
    cudaGetSymbolAddress((void**)&ah,  g_ah);  cudaGetSymbolAddress((void**)&al,  g_al);

    const size_t gemm_smem = (size_t)2 * STG_H * sizeof(__nv_bfloat16);   // 96 KB
    cudaFuncSetAttribute(gemm_bf16x3, cudaFuncAttributeMaxDynamicSharedMemorySize, (int)gemm_smem);
    const size_t attn_smem = ATTN_SMEM_FLOATS * sizeof(float);
    cudaFuncSetAttribute(attn_kernel, cudaFuncAttributeMaxDynamicSharedMemorySize, (int)attn_smem);

    // splits
    {
        int n4 = (MTOT * EMBED) / 4;
        cvt_split<<<(n4 + 255) / 256, 256>>>(x, xh, xl, n4);
    }
    {
        int n4 = (QKVDIM * EMBED) / 4;
        cvt_split<<<(n4 + 255) / 256, 256>>>(w_qkv, wqh, wql, n4);
    }
    {
        int n4 = (EMBED * EMBED) / 4;
        cvt_split<<<(n4 + 255) / 256, 256>>>(w_out, woh, wol, n4);
    }

    // 1) QKV projection
    {
        dim3 grid(QKVDIM / 128, MTOT / 128);
        gemm_bf16x3<<<grid, 256, gemm_smem>>>(xh, xl, wqh, wql, nullptr, qkv_ptr,
                                              MTOT, QKVDIM, GK);
    }

    // 2) flash attention
    {
        dim3 grid(SEQ / 128, NHEADS, BATCH);
        attn_kernel<<<grid, 128, attn_smem>>>(qkv_ptr, attn_ptr);
    }

    // 3) split attention output, then output projection + bias
    {
        int n4 = (MTOT * EMBED) / 4;
        cvt_split<<<(n4 + 255) / 256, 256>>>(attn_ptr, ah, al, n4);
    }
    {
        dim3 grid(EMBED / 128, MTOT / 128);
        gemm_bf16x3<<<grid, 256, gemm_smem>>>(ah, al, woh, wol, b_out, out,
                                              MTOT, EMBED, GK);
    }
}

// round 4
// speedup vs baseline: 3.3274x; 2.5334x over previous
#include <cuda_runtime.h>
#include <cuda_bf16.h>
#include <math.h>
#include <stdint.h>

#define EMBED   1024
#define NHEADS  16
#define HDIM    64
#define SEQ     2048
#define BATCH   2
#define MTOT    (BATCH * SEQ)      // 4096
#define QKVDIM  (3 * EMBED)        // 3072
#define GK      1024
#define ATTN_SCALE 0.125f          // exact power of 2

typedef unsigned long long u64;

// ---------------------------------------------------------------------------
// Scratch (allocation-free __device__ globals)
// ---------------------------------------------------------------------------
__device__ __align__(16) __nv_bfloat16 g_xh [(size_t)MTOT  * EMBED];
__device__ __align__(16) __nv_bfloat16 g_xl [(size_t)MTOT  * EMBED];
__device__ __align__(16) __nv_bfloat16 g_wqh[(size_t)QKVDIM* EMBED];
__device__ __align__(16) __nv_bfloat16 g_wql[(size_t)QKVDIM* EMBED];
__device__ __align__(16) __nv_bfloat16 g_woh[(size_t)EMBED * EMBED];
__device__ __align__(16) __nv_bfloat16 g_wol[(size_t)EMBED * EMBED];
__device__ __align__(16) __nv_bfloat16 g_qvh[(size_t)MTOT  * QKVDIM];  // qkv hi
__device__ __align__(16) __nv_bfloat16 g_qvl[(size_t)MTOT  * QKVDIM];  // qkv lo
__device__ __align__(16) __nv_bfloat16 g_ah [(size_t)MTOT  * EMBED];   // attn out hi
__device__ __align__(16) __nv_bfloat16 g_al [(size_t)MTOT  * EMBED];   // attn out lo

// ---------------------------------------------------------------------------
// helpers
// ---------------------------------------------------------------------------
__device__ __forceinline__ uint32_t smem_u32(const void* p) {
    uint32_t a;
    asm("{ .reg .u64 t; cvta.to.shared.u64 t, %1; cvt.u32.u64 %0, t; }" : "=r"(a) : "l"(p));
    return a;
}
__device__ __forceinline__ void cp16(uint32_t s, const void* g) {
    asm volatile("cp.async.cg.shared.global [%0], [%1], 16;" :: "r"(s), "l"(g));
}
__device__ __forceinline__ void mma2(float* c, const uint32_t* a, uint32_t b0, uint32_t b1) {
    asm volatile(
        "mma.sync.aligned.m16n8k16.row.col.f32.bf16.bf16.f32 "
        "{%0,%1,%2,%3}, {%4,%5,%6,%7}, {%8,%9}, {%0,%1,%2,%3};"
        : "+f"(c[0]), "+f"(c[1]), "+f"(c[2]), "+f"(c[3])
        : "r"(a[0]), "r"(a[1]), "r"(a[2]), "r"(a[3]), "r"(b0), "r"(b1));
}
__device__ __forceinline__ void ldsm4(uint32_t* r, uint32_t addr) {
    asm volatile("ldmatrix.sync.aligned.m8n8.x4.shared.b16 {%0,%1,%2,%3}, [%4];"
        : "=r"(r[0]), "=r"(r[1]), "=r"(r[2]), "=r"(r[3]) : "r"(addr));
}
__device__ __forceinline__ void ldsm4t(uint32_t* r, uint32_t addr) {
    asm volatile("ldmatrix.sync.aligned.m8n8.x4.trans.shared.b16 {%0,%1,%2,%3}, [%4];"
        : "=r"(r[0]), "=r"(r[1]), "=r"(r[2]), "=r"(r[3]) : "r"(addr));
}
// pack two fp32 into bf16x2 (lo = first arg in lower half)
__device__ __forceinline__ uint32_t packbf2(float lo, float hi) {
    uint32_t d;
    asm("cvt.rn.bf16x2.f32 %0, %1, %2;" : "=r"(d) : "f"(hi), "f"(lo));
    return d;
}
#define SWZ128(x) ((x) ^ (((x) >> 3) & 0x70))

// ---------------------------------------------------------------------------
// fp32 -> (bf16 hi, bf16 lo) split
// ---------------------------------------------------------------------------
__global__ void cvt_split(const float* __restrict__ in, __nv_bfloat16* __restrict__ hi,
                          __nv_bfloat16* __restrict__ lo, int n4)
{
    int i = blockIdx.x * blockDim.x + threadIdx.x;
    if (i >= n4) return;
    float4 v = reinterpret_cast<const float4*>(in)[i];
    float h0 = __bfloat162float(__float2bfloat16(v.x));
    float h1 = __bfloat162float(__float2bfloat16(v.y));
    float h2 = __bfloat162float(__float2bfloat16(v.z));
    float h3 = __bfloat162float(__float2bfloat16(v.w));
    uint2 hv, lv;
    hv.x = packbf2(v.x, v.y);      hv.y = packbf2(v.z, v.w);
    lv.x = packbf2(v.x - h0, v.y - h1);
    lv.y = packbf2(v.z - h2, v.w - h3);
    reinterpret_cast<uint2*>(hi)[i] = hv;
    reinterpret_cast<uint2*>(lo)[i] = lv;
}

// ---------------------------------------------------------------------------
// HMMA bf16x3 GEMM: C = A @ B^T (+bias). CTA 128x128, BK=32, 256 threads.
// MODE 0: fp32 out + bias.  MODE 1: split hi/lo bf16 out, cols<qcols scaled 0.125.
// ---------------------------------------------------------------------------
#define BK    32
#define LDT   48
#define TS_H  (128 * LDT)
#define STG_H (4 * TS_H)

__device__ __forceinline__ void store_split(__nv_bfloat16* Ch, __nv_bfloat16* Cl,
                                            size_t off, float v0, float v1)
{
    float h0 = __bfloat162float(__float2bfloat16(v0));
    float h1 = __bfloat162float(__float2bfloat16(v1));
    *reinterpret_cast<uint32_t*>(&Ch[off]) = packbf2(v0, v1);
    *reinterpret_cast<uint32_t*>(&Cl[off]) = packbf2(v0 - h0, v1 - h1);
}

template<int MODE>
__global__ __launch_bounds__(256, 1)
void gemm_bf16x3(const __nv_bfloat16* __restrict__ Ah, const __nv_bfloat16* __restrict__ Al,
                 const __nv_bfloat16* __restrict__ Bh, const __nv_bfloat16* __restrict__ Bl,
                 const float* __restrict__ bias, float* __restrict__ C,
                 __nv_bfloat16* __restrict__ Ch, __nv_bfloat16* __restrict__ Cl,
                 int M, int N, int K, int qcols)
{
    extern __shared__ __align__(16) __nv_bfloat16 sm[];

    const int tid  = threadIdx.x;
    const int wid  = tid >> 5, lane = tid & 31;
    const int bm   = blockIdx.y * 128, bn = blockIdx.x * 128;
    const int wm   = (wid & 3) * 32;
    const int wn   = (wid >> 2) * 64;
    const int g    = lane >> 2;
    const int cp2  = (lane & 3) * 2;

    const uint32_t sb = smem_u32(sm);

    const __nv_bfloat16* gsrc[4] = {
        Ah + (size_t)bm * K, Al + (size_t)bm * K,
        Bh + (size_t)bn * K, Bl + (size_t)bn * K };

    float acc[2][8][4];
#pragma unroll
    for (int i = 0; i < 2; i++)
#pragma unroll
        for (int j = 0; j < 8; j++)
#pragma unroll
            for (int l = 0; l < 4; l++) acc[i][j][l] = 0.f;

    const int nch = K >> 5;

    auto stage_load = [&](int c, int s) {
#pragma unroll
        for (int t = 0; t < 4; t++) {
            const __nv_bfloat16* bp = gsrc[t] + c * BK;
#pragma unroll
            for (int it = 0; it < 2; it++) {
                int idx = it * 256 + tid;
                int row = idx >> 2, cc = idx & 3;
                uint32_t so = sb + (uint32_t)(s * STG_H + t * TS_H + row * LDT + cc * 8) * 2;
                cp16(so, bp + (size_t)row * K + cc * 8);
            }
        }
        asm volatile("cp.async.commit_group;");
    };

    stage_load(0, 0);

    for (int c = 0; c < nch; c++) {
        const int s = c & 1;
        if (c + 1 < nch) {
            stage_load(c + 1, s ^ 1);
            asm volatile("cp.async.wait_group 1;");
        } else {
            asm volatile("cp.async.wait_group 0;");
        }
        __syncthreads();

        const int aoff = s * STG_H;
        const int boff = s * STG_H + 2 * TS_H;

#pragma unroll
        for (int kk = 0; kk < BK; kk += 16) {
            uint32_t af[2][2][4];
            uint32_t bf[8][2][2];
#pragma unroll
            for (int mt = 0; mt < 2; mt++) {
                int r0 = wm + mt * 16 + g;
#pragma unroll
                for (int hl = 0; hl < 2; hl++) {
                    const __nv_bfloat16* base = &sm[aoff + hl * TS_H];
                    af[mt][hl][0] = *(const uint32_t*)&base[(r0    ) * LDT + kk + cp2    ];
                    af[mt][hl][1] = *(const uint32_t*)&base[(r0 + 8) * LDT + kk + cp2    ];
                    af[mt][hl][2] = *(const uint32_t*)&base[(r0    ) * LDT + kk + cp2 + 8];
                    af[mt][hl][3] = *(const uint32_t*)&base[(r0 + 8) * LDT + kk + cp2 + 8];
                }
            }
#pragma unroll
            for (int nt = 0; nt < 8; nt++) {
                int rb = wn + nt * 8 + g;
#pragma unroll
                for (int hl = 0; hl < 2; hl++) {
                    const __nv_bfloat16* base = &sm[boff + hl * TS_H];
                    bf[nt][hl][0] = *(const uint32_t*)&base[rb * LDT + kk + cp2    ];
                    bf[nt][hl][1] = *(const uint32_t*)&base[rb * LDT + kk + cp2 + 8];
                }
            }
#pragma unroll
            for (int mt = 0; mt < 2; mt++)
#pragma unroll
                for (int nt = 0; nt < 8; nt++) {
                    mma2(acc[mt][nt], af[mt][0], bf[nt][0][0], bf[nt][0][1]);
                    mma2(acc[mt][nt], af[mt][0], bf[nt][1][0], bf[nt][1][1]);
                    mma2(acc[mt][nt], af[mt][1], bf[nt][0][0], bf[nt][0][1]);
                }
        }
        __syncthreads();
    }

#pragma unroll
    for (int nt = 0; nt < 8; nt++) {
        int col = bn + wn + nt * 8 + cp2;
        if (MODE == 0) {
            float b0 = bias ? bias[col] : 0.f;
            float b1 = bias ? bias[col + 1] : 0.f;
#pragma unroll
            for (int mt = 0; mt < 2; mt++) {
                int r0 = bm + wm + mt * 16 + g;
                float2 v0 = make_float2(acc[mt][nt][0] + b0, acc[mt][nt][1] + b1);
                float2 v1 = make_float2(acc[mt][nt][2] + b0, acc[mt][nt][3] + b1);
                *reinterpret_cast<float2*>(&C[(size_t)r0 * N + col])       = v0;
                *reinterpret_cast<float2*>(&C[(size_t)(r0 + 8) * N + col]) = v1;
            }
        } else {
            float sc = (col < qcols) ? ATTN_SCALE : 1.0f;
#pragma unroll
            for (int mt = 0; mt < 2; mt++) {
                int r0 = bm + wm + mt * 16 + g;
                store_split(Ch, Cl, (size_t)r0 * N + col,
                            acc[mt][nt][0] * sc, acc[mt][nt][1] * sc);
                store_split(Ch, Cl, (size_t)(r0 + 8) * N + col,
                            acc[mt][nt][2] * sc, acc[mt][nt][3] * sc);
            }
        }
    }
}

// ---------------------------------------------------------------------------
// HMMA flash attention. qv hi/lo: [token][3072] (q pre-scaled by 0.125).
// CTA: 128 queries x 1 head. 8 warps (16 query rows each). Key tile = 64.
// smem: Qh/Ql [128][64] + 2 stages x {Kh,Kl,Vh,Vl}[64][64], SW128 swizzled.
// ---------------------------------------------------------------------------
#define QH_B   0
#define QL_B   16384
#define ASTG0  32768
#define ASTG   32768          // bytes per K/V stage
#define KH_B   0
#define KL_B   8192
#define VH_B   16384
#define VL_B   24576
#define ATTN_SMEM (ASTG0 + 2 * ASTG + 1024)

__global__ __launch_bounds__(256, 1)
void attn_mma(const __nv_bfloat16* __restrict__ qvh, const __nv_bfloat16* __restrict__ qvl,
              __nv_bfloat16* __restrict__ oh, __nv_bfloat16* __restrict__ ol)
{
    extern __shared__ __align__(16) char asmem[];
    const uint32_t sb = (smem_u32(asmem) + 1023u) & ~1023u;

    const int tid  = threadIdx.x;
    const int wid  = tid >> 5, lane = tid & 31;
    const int b    = blockIdx.z, h = blockIdx.y;
    const int q0   = blockIdx.x * 128;
    const int g    = lane >> 2, t4 = lane & 3;
    const int wr   = wid * 16;
    const int m_   = lane >> 3, r_ = lane & 7;

    // --- Q tile load (hi+lo), group 1 ---
    {
        const size_t qb = ((size_t)(b * SEQ + q0)) * QKVDIM + h * HDIM;
#pragma unroll
        for (int it = 0; it < 4; it++) {
            int idx = tid + it * 256;            // 0..1023
            int row = idx >> 3, c = idx & 7;
            uint32_t off = SWZ128((uint32_t)(row * 128 + c * 16));
            cp16(sb + QH_B + off, qvh + qb + (size_t)row * QKVDIM + c * 8);
            cp16(sb + QL_B + off, qvl + qb + (size_t)row * QKVDIM + c * 8);
        }
        asm volatile("cp.async.commit_group;");
    }

    auto stage_load = [&](int kt, int s) {
        const size_t kb = ((size_t)(b * SEQ + kt * 64)) * QKVDIM + h * HDIM;
        const __nv_bfloat16* srcs[4] = {
            qvh + kb + EMBED,     qvl + kb + EMBED,
            qvh + kb + 2 * EMBED, qvl + kb + 2 * EMBED };
#pragma unroll
        for (int t = 0; t < 4; t++) {
#pragma unroll
            for (int it = 0; it < 2; it++) {
                int idx = tid + it * 256;        // 0..511
                int row = idx >> 3, c = idx & 7;
                uint32_t off = SWZ128((uint32_t)(row * 128 + c * 16));
                cp16(sb + ASTG0 + s * ASTG + t * 8192 + off,
                     srcs[t] + (size_t)row * QKVDIM + c * 8);
            }
        }
        asm volatile("cp.async.commit_group;");
    };

    stage_load(0, 0);

    uint32_t qf[2][4][4];
    float oacc[8][4];
#pragma unroll
    for (int i = 0; i < 8; i++)
#pragma unroll
        for (int j = 0; j < 4; j++) oacc[i][j] = 0.f;
    float m0 = -INFINITY, m1 = -INFINITY, l0 = 0.f, l1 = 0.f;

    const int ntile = SEQ / 64;   // 32

    for (int c = 0; c < ntile; c++) {
        const int s = c & 1;
        if (c + 1 < ntile) {
            stage_load(c + 1, s ^ 1);
            asm volatile("cp.async.wait_group 1;");
        } else {
            asm volatile("cp.async.wait_group 0;");
        }
        __syncthreads();

        if (c == 0) {
            // Q fragments (once)
#pragma unroll
            for (int hl = 0; hl < 2; hl++)
#pragma unroll
                for (int ks = 0; ks < 4; ks++) {
                    uint32_t off = SWZ128((uint32_t)(
                        (wr + (m_ & 1) * 8 + r_) * 128 + ks * 32 + (m_ >> 1) * 16));
                    ldsm4(qf[hl][ks], sb + (hl ? QL_B : QH_B) + off);
                }
        }

        const uint32_t stgb = sb + ASTG0 + s * ASTG;

        // --- S = Q K^T (bf16x3) ---
        float sacc[8][4];
#pragma unroll
        for (int i = 0; i < 8; i++)
#pragma unroll
            for (int j = 0; j < 4; j++) sacc[i][j] = 0.f;

#pragma unroll
        for (int ks = 0; ks < 4; ks++) {
#pragma unroll
            for (int ntp = 0; ntp < 4; ntp++) {
                uint32_t off = SWZ128((uint32_t)(
                    (ntp * 16 + (m_ & 1) * 8 + r_) * 128 + ks * 32 + (m_ >> 1) * 16));
                uint32_t kh[4], kl[4];
                ldsm4(kh, stgb + KH_B + off);
                ldsm4(kl, stgb + KL_B + off);
                mma2(sacc[2 * ntp],     qf[0][ks], kh[0], kh[2]);
                mma2(sacc[2 * ntp],     qf[0][ks], kl[0], kl[2]);
                mma2(sacc[2 * ntp],     qf[1][ks], kh[0], kh[2]);
                mma2(sacc[2 * ntp + 1], qf[0][ks], kh[1], kh[3]);
                mma2(sacc[2 * ntp + 1], qf[0][ks], kl[1], kl[3]);
                mma2(sacc[2 * ntp + 1], qf[1][ks], kh[1], kh[3]);
            }
        }

        // --- online softmax (rows g, g+8) ---
        float tm0 = -INFINITY, tm1 = -INFINITY;
#pragma unroll
        for (int nt = 0; nt < 8; nt++) {
            tm0 = fmaxf(tm0, fmaxf(sacc[nt][0], sacc[nt][1]));
            tm1 = fmaxf(tm1, fmaxf(sacc[nt][2], sacc[nt][3]));
        }
        tm0 = fmaxf(tm0, __shfl_xor_sync(0xffffffffu, tm0, 1));
        tm0 = fmaxf(tm0, __shfl_xor_sync(0xffffffffu, tm0, 2));
        tm1 = fmaxf(tm1, __shfl_xor_sync(0xffffffffu, tm1, 1));
        tm1 = fmaxf(tm1, __shfl_xor_sync(0xffffffffu, tm1, 2));

        const float mn0 = fmaxf(m0, tm0), mn1 = fmaxf(m1, tm1);
        const float cr0 = __expf(m0 - mn0), cr1 = __expf(m1 - mn1);
        m0 = mn0; m1 = mn1;

        float rs0 = 0.f, rs1 = 0.f;
#pragma unroll
        for (int nt = 0; nt < 8; nt++) {
            sacc[nt][0] = __expf(sacc[nt][0] - mn0); rs0 += sacc[nt][0];
            sacc[nt][1] = __expf(sacc[nt][1] - mn0); rs0 += sacc[nt][1];
            sacc[nt][2] = __expf(sacc[nt][2] - mn1); rs1 += sacc[nt][2];
            sacc[nt][3] = __expf(sacc[nt][3] - mn1); rs1 += sacc[nt][3];
        }
        rs0 += __shfl_xor_sync(0xffffffffu, rs0, 1);
        rs0 += __shfl_xor_sync(0xffffffffu, rs0, 2);
        rs1 += __shfl_xor_sync(0xffffffffu, rs1, 1);
        rs1 += __shfl_xor_sync(0xffffffffu, rs1, 2);
        l0 = l0 * cr0 + rs0;
        l1 = l1 * cr1 + rs1;

#pragma unroll
        for (int nt = 0; nt < 8; nt++) {
            oacc[nt][0] *= cr0; oacc[nt][1] *= cr0;
            oacc[nt][2] *= cr1; oacc[nt][3] *= cr1;
        }

        // --- O += P V (bf16x3), k = keys ---
#pragma unroll
        for (int ks = 0; ks < 4; ks++) {
            const float* s0 = sacc[2 * ks];
            const float* s1 = sacc[2 * ks + 1];
            uint32_t pah[4], pal[4];
            {
                float v[8] = { s0[0], s0[1], s0[2], s0[3], s1[0], s1[1], s1[2], s1[3] };
#pragma unroll
                for (int i = 0; i < 4; i++) {
                    float x = v[2 * i], y = v[2 * i + 1];
                    float xh = __bfloat162float(__float2bfloat16(x));
                    float yh = __bfloat162float(__float2bfloat16(y));
                    pah[i] = packbf2(x, y);
                    pal[i] = packbf2(x - xh, y - yh);
                }
            }
#pragma unroll
            for (int ntp = 0; ntp < 4; ntp++) {
                uint32_t off = SWZ128((uint32_t)(
                    (ks * 16 + (m_ & 1) * 8 + r_) * 128 + ntp * 32 + (m_ >> 1) * 16));
                uint32_t vh[4], vl[4];
                ldsm4t(vh, stgb + VH_B + off);
                ldsm4t(vl, stgb + VL_B + off);
                mma2(oacc[2 * ntp],     pah, vh[0], vh[1]);
                mma2(oacc[2 * ntp],     pah, vl[0], vl[1]);
                mma2(oacc[2 * ntp],     pal, vh[0], vh[1]);
                mma2(oacc[2 * ntp + 1], pah, vh[2], vh[3]);
                mma2(oacc[2 * ntp + 1], pah, vl[2], vl[3]);
                mma2(oacc[2 * ntp + 1], pal, vh[2], vh[3]);
            }
        }
        __syncthreads();
    }

    // --- epilogue: normalize + split hi/lo ---
    const float il0 = 1.f / l0, il1 = 1.f / l1;
    const size_t ob0 = ((size_t)(b * SEQ + q0 + wr + g)) * EMBED + h * HDIM;
    const size_t ob1 = ob0 + (size_t)8 * EMBED;
#pragma unroll
    for (int nt = 0; nt < 8; nt++) {
        int d = nt * 8 + 2 * t4;
        float v00 = oacc[nt][0] * il0, v01 = oacc[nt][1] * il0;
        float v10 = oacc[nt][2] * il1, v11 = oacc[nt][3] * il1;
        store_split(oh, ol, ob0 + d, v00, v01);
        store_split(oh, ol, ob1 + d, v10, v11);
    }
}

// ---------------------------------------------------------------------------
extern "C" void kernel_launch(void* const* d_in, const int* in_sizes, int n_in,
                              void* d_out, int out_size)
{
    const float* x     = (const float*)d_in[0];
    const float* w_qkv = (const float*)d_in[1];
    const float* w_out = (const float*)d_in[2];
    const float* b_out = (const float*)d_in[3];
    float* out = (float*)d_out;

    __nv_bfloat16 *xh, *xl, *wqh, *wql, *woh, *wol, *qvh, *qvl, *ah, *al;
    cudaGetSymbolAddress((void**)&xh,  g_xh);  cudaGetSymbolAddress((void**)&xl,  g_xl);
    cudaGetSymbolAddress((void**)&wqh, g_wqh); cudaGetSymbolAddress((void**)&wql, g_wql);
    cudaGetSymbolAddress((void**)&woh, g_woh); cudaGetSymbolAddress((void**)&wol, g_wol);
    cudaGetSymbolAddress((void**)&qvh, g_qvh); cudaGetSymbolAddress((void**)&qvl, g_qvl);
    cudaGetSymbolAddress((void**)&ah,  g_ah);  cudaGetSymbolAddress((void**)&al,  g_al);

    const size_t gemm_smem = (size_t)2 * STG_H * sizeof(__nv_bfloat16);   // 96 KB
    cudaFuncSetAttribute(gemm_bf16x3<0>, cudaFuncAttributeMaxDynamicSharedMemorySize, (int)gemm_smem);
    cudaFuncSetAttribute(gemm_bf16x3<1>, cudaFuncAttributeMaxDynamicSharedMemorySize, (int)gemm_smem);
    cudaFuncSetAttribute(attn_mma, cudaFuncAttributeMaxDynamicSharedMemorySize, (int)ATTN_SMEM);

    // operand splits
    {
        int n4 = (MTOT * EMBED) / 4;
        cvt_split<<<(n4 + 255) / 256, 256>>>(x, xh, xl, n4);
    }
    {
        int n4 = (QKVDIM * EMBED) / 4;
        cvt_split<<<(n4 + 255) / 256, 256>>>(w_qkv, wqh, wql, n4);
    }
    {
        int n4 = (EMBED * EMBED) / 4;
        cvt_split<<<(n4 + 255) / 256, 256>>>(w_out, woh, wol, n4);
    }

    // 1) QKV projection -> split hi/lo, Q cols pre-scaled by 0.125
    {
        dim3 grid(QKVDIM / 128, MTOT / 128);
        gemm_bf16x3<1><<<grid, 256, gemm_smem>>>(xh, xl, wqh, wql, nullptr, nullptr,
                                                 qvh, qvl, MTOT, QKVDIM, GK, EMBED);
    }

    // 2) flash attention (HMMA) -> split hi/lo attn output
    {
        dim3 grid(SEQ / 128, NHEADS, BATCH);
        attn_mma<<<grid, 256, ATTN_SMEM>>>(qvh, qvl, ah, al);
    }

    // 3) output projection + bias -> fp32 out
    {
        dim3 grid(EMBED / 128, MTOT / 128);
        gemm_bf16x3<0><<<grid, 256, gemm_smem>>>(ah, al, woh, wol, b_out, out,
                                                 nullptr, nullptr, MTOT, EMBED, GK, 0);
    }
}